// round 15
// baseline (speedup 1.0000x reference)
#include <cuda_runtime.h>
#include <math.h>

#define MAXLEN_  100
#define MAXB     65536
#define MAXROWS  501760            // >= N=500000, row capacity of xg scratch

// ---------------- scratch: xg[n][gate-pair p] as packed f32x2 (u64) ----------------
__device__ unsigned long long d_xg[(size_t)MAXROWS * 128];   // 514 MB

__device__ int d_start[MAXB];
__device__ int d_end[MAXB];
__device__ int d_order[MAXB];
__device__ int d_is64;

// ---------------- packed dual-fp32 FMA (Blackwell FFMA2) ----------------
__device__ __forceinline__ unsigned long long ffma2(unsigned long long a,
                                                    unsigned long long b,
                                                    unsigned long long c) {
    unsigned long long d;
    asm("fma.rn.f32x2 %0, %1, %2, %3;" : "=l"(d) : "l"(a), "l"(b), "l"(c));
    return d;
}
__device__ __forceinline__ unsigned long long pack2(float lo, float hi) {
    unsigned long long d;
    asm("mov.b64 %0, {%1, %2};" : "=l"(d) : "f"(lo), "f"(hi));
    return d;
}
__device__ __forceinline__ void unpack2(unsigned long long v, float& lo, float& hi) {
    asm("mov.b64 {%0, %1}, %2;" : "=f"(lo), "=f"(hi) : "l"(v));
}

__device__ __forceinline__ float sigm_f(float v) { return 1.0f / (1.0f + __expf(-v)); }
__device__ __forceinline__ float tanh_f(float v) { return 1.0f - 2.0f / (__expf(2.0f * v) + 1.0f); }

// ---------------- launch 1: zero bounds + index dtype probe ----------------
__global__ void k_init_detect(const int* __restrict__ w32, int N, int B) {
    int i = blockIdx.x * blockDim.x + threadIdx.x;
    if (i < B) { d_start[i] = 0; d_end[i] = 0; }
    if (i == 0) d_is64 = (w32[N - 1] == 0) ? 1 : 0;   // int64 high word -> 0
}

// ---------------- launch 2: segment boundaries from sorted index ----------------
__global__ void k_bounds(const void* __restrict__ indexv, int N, int B) {
    int i = blockIdx.x * blockDim.x + threadIdx.x;
    if (i >= N) return;
    const int is64 = d_is64;
    int b, bp = -1, bn = -1;
    if (is64) {
        const long long* idx = (const long long*)indexv;
        b = (int)idx[i];
        if (i > 0) bp = (int)idx[i - 1];
        if (i < N - 1) bn = (int)idx[i + 1];
    } else {
        const int* idx = (const int*)indexv;
        b = idx[i];
        if (i > 0) bp = idx[i - 1];
        if (i < N - 1) bn = idx[i + 1];
    }
    if (b < 0 || b >= B) return;
    if (i == 0 || bp != b) d_start[b] = i;
    if (i == N - 1 || bn != b) d_end[b] = i + 1;
}

// =======================================================================
// launch 3: k_xgemm_rank — 8 rows/thread (32 acc regs -> ptxas slack).
//  Block 0 prologue: descending-length counting sort -> d_order.
//  256 threads = (q = t&63: gate pairs 2q,2q+1) x (rh = t>>6: 8-row octet),
//  32-row tiles.  smem: sWa 32KB | sWb 32KB | sX dup 16KB = 80.25KB
// =======================================================================
#define XG_SMEM (32768 + 32768 + 16384)

extern __shared__ unsigned char smem_raw[];

__global__ __launch_bounds__(256, 2)
void k_xgemm_rank(const float* __restrict__ x,
                  const float* __restrict__ W_ih,
                  const float* __restrict__ b_ih,
                  const float* __restrict__ b_hh,
                  int N, int B) {
    if (blockIdx.x == 0) {
        __shared__ int hist[MAXLEN_ + 1], offs[MAXLEN_ + 1], curs[MAXLEN_ + 1];
        const int tt = threadIdx.x;
        for (int l = tt; l <= MAXLEN_; l += 256) { hist[l] = 0; curs[l] = 0; }
        __syncthreads();
        for (int b = tt; b < B; b += 256) {
            int l = d_end[b] - d_start[b];
            l = min(max(l, 0), MAXLEN_);
            atomicAdd(&hist[l], 1);
        }
        __syncthreads();
        if (tt == 0) {
            int acc = 0;
            for (int l = MAXLEN_; l >= 0; --l) { offs[l] = acc; acc += hist[l]; }
        }
        __syncthreads();
        for (int b = tt; b < B; b += 256) {
            int l = d_end[b] - d_start[b];
            l = min(max(l, 0), MAXLEN_);
            int p = offs[l] + atomicAdd(&curs[l], 1);
            d_order[p] = b;
        }
    }

    float4* sWa = (float4*)smem_raw;                    // [k2*64+q] gates 4q,4q+1
    float4* sWb = (float4*)(smem_raw + 32768);          // [k2*64+q] gates 4q+2,4q+3
    float4* sX  = (float4*)(smem_raw + 65536);          // [r*32+k2] dup, r<32
    const ulonglong2* sWau = (const ulonglong2*)sWa;
    const ulonglong2* sWbu = (const ulonglong2*)sWb;
    const ulonglong2* sXu  = (const ulonglong2*)sX;

    const int t = threadIdx.x;
    const int q  = t & 63;
    const int rh = t >> 6;      // 0..3 -> rows rh*8 .. rh*8+7

    for (int idx = t; idx < 2048; idx += 256) {
        int k2 = idx >> 6, qq = idx & 63;
        int ga = 4 * qq;
        sWa[idx] = make_float4(W_ih[ga * 64 + 2 * k2],       W_ih[(ga + 1) * 64 + 2 * k2],
                               W_ih[ga * 64 + 2 * k2 + 1],   W_ih[(ga + 1) * 64 + 2 * k2 + 1]);
        int gb = 4 * qq + 2;
        sWb[idx] = make_float4(W_ih[gb * 64 + 2 * k2],       W_ih[(gb + 1) * 64 + 2 * k2],
                               W_ih[gb * 64 + 2 * k2 + 1],   W_ih[(gb + 1) * 64 + 2 * k2 + 1]);
    }
    const unsigned long long bias0 =
        pack2(b_ih[4 * q] + b_hh[4 * q],         b_ih[4 * q + 1] + b_hh[4 * q + 1]);
    const unsigned long long bias1 =
        pack2(b_ih[4 * q + 2] + b_hh[4 * q + 2], b_ih[4 * q + 3] + b_hh[4 * q + 3]);

    const int ntiles = (N + 31) >> 5;
    for (int tile = blockIdx.x; tile < ntiles; tile += gridDim.x) {
        const int row0 = tile << 5;
        __syncthreads();   // protect previous iteration's sX reads
        #pragma unroll
        for (int i = 0; i < 4; ++i) {
            int idx = t + i * 256;            // 0..1023
            int r = idx >> 5, k2 = idx & 31;
            int row = row0 + r;
            float2 v = make_float2(0.f, 0.f);
            if (row < N) v = ((const float2*)x)[(size_t)row * 32 + k2];
            sX[r * 32 + k2] = make_float4(v.x, v.x, v.y, v.y);
        }
        __syncthreads();

        unsigned long long acc0[8], acc1[8];
        #pragma unroll
        for (int r = 0; r < 8; ++r) { acc0[r] = bias0; acc1[r] = bias1; }

        const int rbase = rh * 8;
        #pragma unroll 2
        for (int k2 = 0; k2 < 32; ++k2) {
            ulonglong2 wa = sWau[k2 * 64 + q];
            ulonglong2 wb = sWbu[k2 * 64 + q];
            #pragma unroll
            for (int r = 0; r < 8; ++r) {
                ulonglong2 v = sXu[(rbase + r) * 32 + k2];   // warp-uniform -> broadcast
                acc0[r] = ffma2(wa.x, v.x, acc0[r]);
                acc0[r] = ffma2(wa.y, v.y, acc0[r]);
                acc1[r] = ffma2(wb.x, v.x, acc1[r]);
                acc1[r] = ffma2(wb.y, v.y, acc1[r]);
            }
        }

        #pragma unroll
        for (int r = 0; r < 8; ++r) {
            int row = row0 + rbase + r;
            if (row < N) {
                ulonglong2 o; o.x = acc0[r]; o.y = acc1[r];
                *(ulonglong2*)&d_xg[(size_t)row * 128 + 2 * q] = o;   // STG.128
            }
        }
    }
}

// =======================================================================
// launch 4 (ncu capture slot): k_lstm — low-register recurrence.
// Thread = (u = t&31: unit pair) x (g8 = t>>5: 2-segment group).
// 4 gate-pairs x 2 segs per thread: acc[8]+cur[8] = 32 regs.
// Double-buffered sV -> ONE __syncthreads per step.
// Frozen segs rewrite their held h every step, so both buffers stay fresh.
// G=16 segs/block, 256 threads, 2 blocks/SM.
//  smem: sW 64KB [k2*128+p] | sV0 8KB | sV1 8KB = 80.25KB
// =======================================================================
#define G        16
#define LT       256
#define L_SMEM   (65536 + 8192 + 8192)

__global__ __launch_bounds__(LT, 2)
void k_lstm(const float* __restrict__ W_hh,
            float* __restrict__ out,
            int B, int N) {
    float4* sW  = (float4*)smem_raw;                      // [k2*128+p], 64KB
    float4* sV0 = (float4*)(smem_raw + 65536);            // [seg*32+u] dup-h
    float4* sV1 = (float4*)(smem_raw + 65536 + 8192);
    const ulonglong2* sWu = (const ulonglong2*)sW;
    __shared__ int s_start[G], s_len[G], s_segid[G];

    const int t = threadIdx.x;
    const int u  = t & 31;      // unit pair: units 2u, 2u+1
    const int g8 = t >> 5;      // segment group: segs 2g8, 2g8+1
    const int se0 = 2 * g8, se1 = 2 * g8 + 1;

    // ---- stage W_hh pairs ----
    for (int idx = t; idx < 4096; idx += LT) {
        int k2 = idx >> 7, pp = idx & 127;
        sW[idx] = make_float4(W_hh[(2 * pp)     * 64 + 2 * k2],
                              W_hh[(2 * pp + 1) * 64 + 2 * k2],
                              W_hh[(2 * pp)     * 64 + 2 * k2 + 1],
                              W_hh[(2 * pp + 1) * 64 + 2 * k2 + 1]);
    }
    // ---- segment metadata from precomputed order ----
    if (t < G) {
        int gi  = blockIdx.x * G + t;
        int seg = (gi < B) ? d_order[gi] : -1;
        int st  = (seg >= 0) ? d_start[seg] : 0;
        int en  = (seg >= 0) ? d_end[seg] : 0;
        int ln  = en - st;
        ln = min(max(ln, 0), MAXLEN_);
        if (st < 0) st = 0;
        if (st > N) st = N;
        if (ln > N - st) ln = N - st;
        s_segid[t] = seg;
        s_start[t] = st;
        s_len[t]   = ln;
    }
    for (int i = t; i < G * 32; i += LT) {
        sV0[i] = make_float4(0.f, 0.f, 0.f, 0.f);
        sV1[i] = make_float4(0.f, 0.f, 0.f, 0.f);
    }
    __syncthreads();

    int nsteps = 0;
    #pragma unroll
    for (int s = 0; s < G; ++s) nsteps = max(nsteps, s_len[s]);

    const int st0 = s_start[se0], st1 = s_start[se1];
    const int ln0 = s_len[se0],   ln1 = s_len[se1];

    float c[4]    = {0.f, 0.f, 0.f, 0.f};   // [seg][unit01]
    float hreg[4] = {0.f, 0.f, 0.f, 0.f};

    // xg for step 0: index [seg*4 + gate(i,f,g,o)]
    unsigned long long cur[8];
    #pragma unroll
    for (int blk = 0; blk < 4; ++blk) {
        cur[blk]     = (0 < ln0) ? d_xg[(size_t)st0 * 128 + blk * 32 + u] : 0ull;
        cur[4 + blk] = (0 < ln1) ? d_xg[(size_t)st1 * 128 + blk * 32 + u] : 0ull;
    }

    for (int step = 0; step < nsteps; ++step) {
        const ulonglong2* sVr = (const ulonglong2*)((step & 1) ? sV1 : sV0);
        float4*           sVw = (step & 1) ? sV0 : sV1;

        // consume cur into acc, then prefetch next step (hidden under GEMV)
        unsigned long long acc[8];
        #pragma unroll
        for (int i = 0; i < 8; ++i) acc[i] = cur[i];
        {
            int ns = step + 1;
            #pragma unroll
            for (int blk = 0; blk < 4; ++blk) {
                cur[blk]     = (ns < ln0) ? d_xg[(size_t)(st0 + ns) * 128 + blk * 32 + u] : 0ull;
                cur[4 + blk] = (ns < ln1) ? d_xg[(size_t)(st1 + ns) * 128 + blk * 32 + u] : 0ull;
            }
        }

        // ---- GEMV over h (K=64): 4 gate-pairs x 2 segments ----
        #pragma unroll 2
        for (int k2 = 0; k2 < 32; ++k2) {
            ulonglong2 w0 = sWu[k2 * 128 + u];          // i-pair
            ulonglong2 w1 = sWu[k2 * 128 + 32 + u];     // f-pair
            ulonglong2 w2 = sWu[k2 * 128 + 64 + u];     // g-pair
            ulonglong2 w3 = sWu[k2 * 128 + 96 + u];     // o-pair
            ulonglong2 v0 = sVr[se0 * 32 + k2];         // warp-uniform -> broadcast
            ulonglong2 v1 = sVr[se1 * 32 + k2];
            acc[0] = ffma2(w0.x, v0.x, acc[0]); acc[0] = ffma2(w0.y, v0.y, acc[0]);
            acc[1] = ffma2(w1.x, v0.x, acc[1]); acc[1] = ffma2(w1.y, v0.y, acc[1]);
            acc[2] = ffma2(w2.x, v0.x, acc[2]); acc[2] = ffma2(w2.y, v0.y, acc[2]);
            acc[3] = ffma2(w3.x, v0.x, acc[3]); acc[3] = ffma2(w3.y, v0.y, acc[3]);
            acc[4] = ffma2(w0.x, v1.x, acc[4]); acc[4] = ffma2(w0.y, v1.y, acc[4]);
            acc[5] = ffma2(w1.x, v1.x, acc[5]); acc[5] = ffma2(w1.y, v1.y, acc[5]);
            acc[6] = ffma2(w2.x, v1.x, acc[6]); acc[6] = ffma2(w2.y, v1.y, acc[6]);
            acc[7] = ffma2(w3.x, v1.x, acc[7]); acc[7] = ffma2(w3.y, v1.y, acc[7]);
        }

        // ---- cell update (freeze finished segs; ALWAYS write h to wbuf) ----
        if (step < ln0) {
            float ilo, ihi, flo, fhi, glo, ghi, olo, ohi;
            unpack2(acc[0], ilo, ihi); unpack2(acc[1], flo, fhi);
            unpack2(acc[2], glo, ghi); unpack2(acc[3], olo, ohi);
            float cn0 = sigm_f(flo) * c[0] + sigm_f(ilo) * tanh_f(glo);
            float cn1 = sigm_f(fhi) * c[1] + sigm_f(ihi) * tanh_f(ghi);
            hreg[0] = sigm_f(olo) * tanh_f(cn0);
            hreg[1] = sigm_f(ohi) * tanh_f(cn1);
            c[0] = cn0; c[1] = cn1;
        }
        sVw[se0 * 32 + u] = make_float4(hreg[0], hreg[0], hreg[1], hreg[1]);
        if (step < ln1) {
            float ilo, ihi, flo, fhi, glo, ghi, olo, ohi;
            unpack2(acc[4], ilo, ihi); unpack2(acc[5], flo, fhi);
            unpack2(acc[6], glo, ghi); unpack2(acc[7], olo, ohi);
            float cn0 = sigm_f(flo) * c[2] + sigm_f(ilo) * tanh_f(glo);
            float cn1 = sigm_f(fhi) * c[3] + sigm_f(ihi) * tanh_f(ghi);
            hreg[2] = sigm_f(olo) * tanh_f(cn0);
            hreg[3] = sigm_f(ohi) * tanh_f(cn1);
            c[2] = cn0; c[3] = cn1;
        }
        sVw[se1 * 32 + u] = make_float4(hreg[2], hreg[2], hreg[3], hreg[3]);

        __syncthreads();   // single barrier: wbuf complete before next GEMV reads it
    }

    // ---- emit last hidden from registers (zero-length segs emit 0) ----
    if (s_segid[se0] >= 0) {
        out[(size_t)s_segid[se0] * 64 + 2 * u]     = hreg[0];
        out[(size_t)s_segid[se0] * 64 + 2 * u + 1] = hreg[1];
    }
    if (s_segid[se1] >= 0) {
        out[(size_t)s_segid[se1] * 64 + 2 * u]     = hreg[2];
        out[(size_t)s_segid[se1] * 64 + 2 * u + 1] = hreg[3];
    }
}

extern "C" void kernel_launch(void* const* d_in, const int* in_sizes, int n_in,
                              void* d_out, int out_size) {
    const float* x    = (const float*)d_in[0];
    const float* W_ih = (const float*)d_in[1];
    const float* W_hh = (const float*)d_in[2];
    const float* b_ih = (const float*)d_in[3];
    const float* b_hh = (const float*)d_in[4];
    const void*  indexv = d_in[5];
    float* out = (float*)d_out;

    int N = in_sizes[0] / 64;
    int B = out_size / 64;
    if (B > MAXB) B = MAXB;
    if (N > MAXROWS) N = MAXROWS;

    cudaFuncSetAttribute(k_xgemm_rank, cudaFuncAttributeMaxDynamicSharedMemorySize, XG_SMEM);
    cudaFuncSetAttribute(k_lstm,       cudaFuncAttributeMaxDynamicSharedMemorySize, L_SMEM);

    // exactly 4 launches; ncu capture slot (#4) = k_lstm
    k_init_detect<<<(B + 255) / 256, 256>>>((const int*)indexv, N, B);
    k_bounds<<<(N + 255) / 256, 256>>>(indexv, N, B);
    k_xgemm_rank<<<296, 256, XG_SMEM>>>(x, W_ih, b_ih, b_hh, N, B);

    int nblk = (B + G - 1) / G;
    k_lstm<<<nblk, LT, L_SMEM>>>(W_hh, out, B, N);
}

// round 16
// speedup vs baseline: 1.1035x; 1.1035x over previous
#include <cuda_runtime.h>
#include <math.h>

#define MAXLEN_  100
#define MAXB     65536
#define MAXROWS  501760            // >= N=500000, row capacity of xg scratch

// ---------------- scratch: xg[n][gate-pair p] as packed f32x2 (u64) ----------------
__device__ unsigned long long d_xg[(size_t)MAXROWS * 128];   // 514 MB

__device__ int d_start[MAXB];
__device__ int d_end[MAXB];
__device__ int d_order[MAXB];
__device__ int d_is64;

// ---------------- packed dual-fp32 FMA (Blackwell FFMA2) ----------------
__device__ __forceinline__ unsigned long long ffma2(unsigned long long a,
                                                    unsigned long long b,
                                                    unsigned long long c) {
    unsigned long long d;
    asm("fma.rn.f32x2 %0, %1, %2, %3;" : "=l"(d) : "l"(a), "l"(b), "l"(c));
    return d;
}
__device__ __forceinline__ unsigned long long pack2(float lo, float hi) {
    unsigned long long d;
    asm("mov.b64 %0, {%1, %2};" : "=l"(d) : "f"(lo), "f"(hi));
    return d;
}
__device__ __forceinline__ void unpack2(unsigned long long v, float& lo, float& hi) {
    asm("mov.b64 {%0, %1}, %2;" : "=f"(lo), "=f"(hi) : "l"(v));
}

// ---------------- activations ----------------
// k_lstm: hardware tanh (MUFU.TANH, sm_75+). 1 MUFU each, no RCP chains.
__device__ __forceinline__ float tanh_a(float v) {
    float r;
    asm("tanh.approx.f32 %0, %1;" : "=f"(r) : "f"(v));
    return r;
}
__device__ __forceinline__ float sigm_a(float v) {
    return fmaf(tanh_a(0.5f * v), 0.5f, 0.5f);   // sigma(x) = 0.5*tanh(x/2)+0.5
}

// ---------------- launch 1: zero bounds + index dtype probe ----------------
__global__ void k_init_detect(const int* __restrict__ w32, int N, int B) {
    int i = blockIdx.x * blockDim.x + threadIdx.x;
    if (i < B) { d_start[i] = 0; d_end[i] = 0; }
    if (i == 0) d_is64 = (w32[N - 1] == 0) ? 1 : 0;   // int64 high word -> 0
}

// ---------------- launch 2: segment boundaries from sorted index ----------------
__global__ void k_bounds(const void* __restrict__ indexv, int N, int B) {
    int i = blockIdx.x * blockDim.x + threadIdx.x;
    if (i >= N) return;
    const int is64 = d_is64;
    int b, bp = -1, bn = -1;
    if (is64) {
        const long long* idx = (const long long*)indexv;
        b = (int)idx[i];
        if (i > 0) bp = (int)idx[i - 1];
        if (i < N - 1) bn = (int)idx[i + 1];
    } else {
        const int* idx = (const int*)indexv;
        b = idx[i];
        if (i > 0) bp = idx[i - 1];
        if (i < N - 1) bn = idx[i + 1];
    }
    if (b < 0 || b >= B) return;
    if (i == 0 || bp != b) d_start[b] = i;
    if (i == N - 1 || bn != b) d_end[b] = i + 1;
}

// =======================================================================
// launch 3: k_xgemm_rank (unchanged from R14 — keep the experiment clean)
// =======================================================================
#define XG_SMEM (32768 + 32768 + 16384)

extern __shared__ unsigned char smem_raw[];

__global__ __launch_bounds__(256, 2)
void k_xgemm_rank(const float* __restrict__ x,
                  const float* __restrict__ W_ih,
                  const float* __restrict__ b_ih,
                  const float* __restrict__ b_hh,
                  int N, int B) {
    if (blockIdx.x == 0) {
        __shared__ int hist[MAXLEN_ + 1], offs[MAXLEN_ + 1], curs[MAXLEN_ + 1];
        const int tt = threadIdx.x;
        for (int l = tt; l <= MAXLEN_; l += 256) { hist[l] = 0; curs[l] = 0; }
        __syncthreads();
        for (int b = tt; b < B; b += 256) {
            int l = d_end[b] - d_start[b];
            l = min(max(l, 0), MAXLEN_);
            atomicAdd(&hist[l], 1);
        }
        __syncthreads();
        if (tt == 0) {
            int acc = 0;
            for (int l = MAXLEN_; l >= 0; --l) { offs[l] = acc; acc += hist[l]; }
        }
        __syncthreads();
        for (int b = tt; b < B; b += 256) {
            int l = d_end[b] - d_start[b];
            l = min(max(l, 0), MAXLEN_);
            int p = offs[l] + atomicAdd(&curs[l], 1);
            d_order[p] = b;
        }
    }

    float4* sWa = (float4*)smem_raw;                    // [k2*64+q] gates 4q,4q+1
    float4* sWb = (float4*)(smem_raw + 32768);          // [k2*64+q] gates 4q+2,4q+3
    float4* sX  = (float4*)(smem_raw + 65536);          // [r*32+k2] dup, r<32
    const ulonglong2* sWau = (const ulonglong2*)sWa;
    const ulonglong2* sWbu = (const ulonglong2*)sWb;
    const ulonglong2* sXu  = (const ulonglong2*)sX;

    const int t = threadIdx.x;
    const int q  = t & 63;
    const int rh = t >> 6;      // 0..3 -> rows rh*8 .. rh*8+7

    for (int idx = t; idx < 2048; idx += 256) {
        int k2 = idx >> 6, qq = idx & 63;
        int ga = 4 * qq;
        sWa[idx] = make_float4(W_ih[ga * 64 + 2 * k2],       W_ih[(ga + 1) * 64 + 2 * k2],
                               W_ih[ga * 64 + 2 * k2 + 1],   W_ih[(ga + 1) * 64 + 2 * k2 + 1]);
        int gb = 4 * qq + 2;
        sWb[idx] = make_float4(W_ih[gb * 64 + 2 * k2],       W_ih[(gb + 1) * 64 + 2 * k2],
                               W_ih[gb * 64 + 2 * k2 + 1],   W_ih[(gb + 1) * 64 + 2 * k2 + 1]);
    }
    const unsigned long long bias0 =
        pack2(b_ih[4 * q] + b_hh[4 * q],         b_ih[4 * q + 1] + b_hh[4 * q + 1]);
    const unsigned long long bias1 =
        pack2(b_ih[4 * q + 2] + b_hh[4 * q + 2], b_ih[4 * q + 3] + b_hh[4 * q + 3]);

    const int ntiles = (N + 31) >> 5;
    for (int tile = blockIdx.x; tile < ntiles; tile += gridDim.x) {
        const int row0 = tile << 5;
        __syncthreads();
        #pragma unroll
        for (int i = 0; i < 4; ++i) {
            int idx = t + i * 256;
            int r = idx >> 5, k2 = idx & 31;
            int row = row0 + r;
            float2 v = make_float2(0.f, 0.f);
            if (row < N) v = ((const float2*)x)[(size_t)row * 32 + k2];
            sX[r * 32 + k2] = make_float4(v.x, v.x, v.y, v.y);
        }
        __syncthreads();

        unsigned long long acc0[8], acc1[8];
        #pragma unroll
        for (int r = 0; r < 8; ++r) { acc0[r] = bias0; acc1[r] = bias1; }

        const int rbase = rh * 8;
        #pragma unroll 2
        for (int k2 = 0; k2 < 32; ++k2) {
            ulonglong2 wa = sWau[k2 * 64 + q];
            ulonglong2 wb = sWbu[k2 * 64 + q];
            #pragma unroll
            for (int r = 0; r < 8; ++r) {
                ulonglong2 v = sXu[(rbase + r) * 32 + k2];   // warp-uniform -> broadcast
                acc0[r] = ffma2(wa.x, v.x, acc0[r]);
                acc0[r] = ffma2(wa.y, v.y, acc0[r]);
                acc1[r] = ffma2(wb.x, v.x, acc1[r]);
                acc1[r] = ffma2(wb.y, v.y, acc1[r]);
            }
        }

        #pragma unroll
        for (int r = 0; r < 8; ++r) {
            int row = row0 + rbase + r;
            if (row < N) {
                ulonglong2 o; o.x = acc0[r]; o.y = acc1[r];
                *(ulonglong2*)&d_xg[(size_t)row * 128 + 2 * q] = o;   // STG.128
            }
        }
    }
}

// =======================================================================
// launch 4 (ncu capture slot): k_lstm — R14 structure (G=32, 4 segs x 4
// gate-pairs per thread, crossbar-balanced) + MUFU.TANH activations.
//  smem: sW 64KB [k2*128+p] | sV dup-h 16KB [seg*32+k2] = 80.3KB, 2 blk/SM
// =======================================================================
#define G        32
#define LT       256
#define L_SMEM   (65536 + 16384)

__global__ __launch_bounds__(LT, 2)
void k_lstm(const float* __restrict__ W_hh,
            float* __restrict__ out,
            int B, int N) {
    float4* sW = (float4*)smem_raw;                       // [k2*128+p], 64KB
    float4* sV = (float4*)(smem_raw + 65536);             // [seg*32+k2], 16KB
    const ulonglong2* sWu = (const ulonglong2*)sW;
    const ulonglong2* sVu = (const ulonglong2*)sV;
    __shared__ int s_start[G], s_len[G], s_segid[G];

    const int t = threadIdx.x;
    const int u  = t & 31;      // unit pair: units 2u, 2u+1
    const int sq = t >> 5;      // segment group: segs 4sq .. 4sq+3
    const int se0 = 4 * sq;

    // ---- stage W_hh pairs ----
    for (int idx = t; idx < 4096; idx += LT) {
        int k2 = idx >> 7, pp = idx & 127;
        sW[idx] = make_float4(W_hh[(2 * pp)     * 64 + 2 * k2],
                              W_hh[(2 * pp + 1) * 64 + 2 * k2],
                              W_hh[(2 * pp)     * 64 + 2 * k2 + 1],
                              W_hh[(2 * pp + 1) * 64 + 2 * k2 + 1]);
    }
    // ---- segment metadata from precomputed order ----
    if (t < G) {
        int gi  = blockIdx.x * G + t;
        int seg = (gi < B) ? d_order[gi] : -1;
        int st  = (seg >= 0) ? d_start[seg] : 0;
        int en  = (seg >= 0) ? d_end[seg] : 0;
        int ln  = en - st;
        ln = min(max(ln, 0), MAXLEN_);
        if (st < 0) st = 0;
        if (st > N) st = N;
        if (ln > N - st) ln = N - st;
        s_segid[t] = seg;
        s_start[t] = st;
        s_len[t]   = ln;
    }
    for (int i = t; i < G * 32; i += LT) sV[i] = make_float4(0.f, 0.f, 0.f, 0.f);
    __syncthreads();

    int nsteps = 0;
    #pragma unroll
    for (int s = 0; s < G; ++s) nsteps = max(nsteps, s_len[s]);

    int st_[4], ln_[4];
    #pragma unroll
    for (int j = 0; j < 4; ++j) { st_[j] = s_start[se0 + j]; ln_[j] = s_len[se0 + j]; }

    // cell state: c[j*2+h] = c for seg j, unit 2u+h
    float c[8] = {0.f, 0.f, 0.f, 0.f, 0.f, 0.f, 0.f, 0.f};

    // xg for step 0: acc index [j*4 + blk], blk = gate type (i,f,g,o)
    unsigned long long cur[16];
    #pragma unroll
    for (int j = 0; j < 4; ++j)
        #pragma unroll
        for (int blk = 0; blk < 4; ++blk)
            cur[j * 4 + blk] = (0 < ln_[j]) ? d_xg[(size_t)st_[j] * 128 + blk * 32 + u] : 0ull;

    for (int step = 0; step < nsteps; ++step) {
        // consume cur into acc, then prefetch next step (hidden under GEMV)
        unsigned long long acc[16];
        #pragma unroll
        for (int i = 0; i < 16; ++i) acc[i] = cur[i];
        {
            int ns = step + 1;
            #pragma unroll
            for (int j = 0; j < 4; ++j)
                #pragma unroll
                for (int blk = 0; blk < 4; ++blk)
                    cur[j * 4 + blk] = (ns < ln_[j])
                        ? d_xg[(size_t)(st_[j] + ns) * 128 + blk * 32 + u] : 0ull;
        }

        // ---- GEMV over h (K=64): 4 gate-pairs x 4 segments ----
        #pragma unroll 2
        for (int k2 = 0; k2 < 32; ++k2) {
            ulonglong2 w0 = sWu[k2 * 128 + u];          // i-pair
            ulonglong2 w1 = sWu[k2 * 128 + 32 + u];     // f-pair
            ulonglong2 w2 = sWu[k2 * 128 + 64 + u];     // g-pair
            ulonglong2 w3 = sWu[k2 * 128 + 96 + u];     // o-pair
            #pragma unroll
            for (int j = 0; j < 4; ++j) {
                ulonglong2 v = sVu[(se0 + j) * 32 + k2];   // warp-uniform -> broadcast
                acc[j * 4 + 0] = ffma2(w0.x, v.x, acc[j * 4 + 0]);
                acc[j * 4 + 0] = ffma2(w0.y, v.y, acc[j * 4 + 0]);
                acc[j * 4 + 1] = ffma2(w1.x, v.x, acc[j * 4 + 1]);
                acc[j * 4 + 1] = ffma2(w1.y, v.y, acc[j * 4 + 1]);
                acc[j * 4 + 2] = ffma2(w2.x, v.x, acc[j * 4 + 2]);
                acc[j * 4 + 2] = ffma2(w2.y, v.y, acc[j * 4 + 2]);
                acc[j * 4 + 3] = ffma2(w3.x, v.x, acc[j * 4 + 3]);
                acc[j * 4 + 3] = ffma2(w3.y, v.y, acc[j * 4 + 3]);
            }
        }
        __syncthreads();   // all GEMV reads of sV complete

        // ---- cell update (MUFU.TANH path); write new h to sV ----
        #pragma unroll
        for (int j = 0; j < 4; ++j) {
            if (step < ln_[j]) {
                float ilo, ihi, flo, fhi, glo, ghi, olo, ohi;
                unpack2(acc[j * 4 + 0], ilo, ihi);
                unpack2(acc[j * 4 + 1], flo, fhi);
                unpack2(acc[j * 4 + 2], glo, ghi);
                unpack2(acc[j * 4 + 3], olo, ohi);
                float cn0 = sigm_a(flo) * c[j * 2]     + sigm_a(ilo) * tanh_a(glo);
                float cn1 = sigm_a(fhi) * c[j * 2 + 1] + sigm_a(ihi) * tanh_a(ghi);
                float h0 = sigm_a(olo) * tanh_a(cn0);
                float h1 = sigm_a(ohi) * tanh_a(cn1);
                c[j * 2] = cn0; c[j * 2 + 1] = cn1;
                sV[(se0 + j) * 32 + u] = make_float4(h0, h0, h1, h1);
            }
        }
        __syncthreads();   // h visible before next GEMV
    }

    // ---- emit last hidden from sV (zero-length segments emit 0) ----
    #pragma unroll
    for (int j = 0; j < 4; ++j) {
        if (s_segid[se0 + j] >= 0) {
            float4 hv = sV[(se0 + j) * 32 + u];
            out[(size_t)s_segid[se0 + j] * 64 + 2 * u]     = hv.x;
            out[(size_t)s_segid[se0 + j] * 64 + 2 * u + 1] = hv.z;
        }
    }
}

extern "C" void kernel_launch(void* const* d_in, const int* in_sizes, int n_in,
                              void* d_out, int out_size) {
    const float* x    = (const float*)d_in[0];
    const float* W_ih = (const float*)d_in[1];
    const float* W_hh = (const float*)d_in[2];
    const float* b_ih = (const float*)d_in[3];
    const float* b_hh = (const float*)d_in[4];
    const void*  indexv = d_in[5];
    float* out = (float*)d_out;

    int N = in_sizes[0] / 64;
    int B = out_size / 64;
    if (B > MAXB) B = MAXB;
    if (N > MAXROWS) N = MAXROWS;

    cudaFuncSetAttribute(k_xgemm_rank, cudaFuncAttributeMaxDynamicSharedMemorySize, XG_SMEM);
    cudaFuncSetAttribute(k_lstm,       cudaFuncAttributeMaxDynamicSharedMemorySize, L_SMEM);

    // exactly 4 launches; ncu capture slot (#4) = k_lstm
    k_init_detect<<<(B + 255) / 256, 256>>>((const int*)indexv, N, B);
    k_bounds<<<(N + 255) / 256, 256>>>(indexv, N, B);
    k_xgemm_rank<<<296, 256, XG_SMEM>>>(x, W_ih, b_ih, b_hh, N, B);

    int nblk = (B + G - 1) / G;
    k_lstm<<<nblk, LT, L_SMEM>>>(W_hh, out, B, N);
}